// round 10
// baseline (speedup 1.0000x reference)
#include <cuda_runtime.h>
#include <cstdint>

// ---------------------------------------------------------------------------
// Cluster-DSMEM design: the 800 KB packed node table {T,cp} is distributed
// across a cluster of 8 CTAs (12,500 nodes x 8 B = 100,000 B SMEM each).
// Gathers become mapa + ld.shared::cluster instead of 32-wavefront L1tex
// divergent global loads (the measured bottleneck, L1=75% across R5-R7).
// ---------------------------------------------------------------------------

#define CLUSTER   8
#define NPC       12500u          // nodes per CTA slice; 8*12500 = 100000
#define THREADS   768
#define GRID_CTAS 296             // 37 clusters * 8; ~2 CTAs/SM resource-wise

// Fallback-path table (old design), used only if shape != expected.
#define MAX_NODES 131072
__device__ float2 g_tc[MAX_NODES];

// ---------------- common math ----------------
__device__ __forceinline__ void edge_op(float Ts, float cps, float Td, float cpd,
                                        float L, float C, float A, float t,
                                        int si, int di, float* out) {
    float dT = Ts - Td;
    if (dT > 0.0f) {                                   // relu: E==0 exactly otherwise
        float x   = __fdividef(dT, L) * C;
        float hfd = exp2f(0.33333334f * __log2f(x));   // cbrt via 2 MUFU
        float Ec  = hfd * A * t;
        float ccp = __fdividef(cpd * cps, cpd + cps);
        float E   = fminf(Ec, dT * ccp);
        atomicAdd(out + di,  E);
        atomicAdd(out + si, -E);
    }
}

// ---------------- cluster path ----------------
__device__ __forceinline__ uint32_t smem_u32(const void* p) {
    uint32_t a;
    asm("{ .reg .u64 t; cvta.to.shared.u64 t, %1; cvt.u32.u64 %0, t; }"
        : "=r"(a) : "l"(p));
    return a;
}

// node -> owning CTA rank + remote SMEM read via DSMEM.
__device__ __forceinline__ float2 dsm_read(uint32_t smem_base, uint32_t node) {
    uint32_t c   = node / NPC;              // const-div -> mulhi+shift
    uint32_t off = node - c * NPC;
    uint32_t laddr = smem_base + off * 8u;
    uint32_t raddr;
    asm("mapa.shared::cluster.u32 %0, %1, %2;" : "=r"(raddr) : "r"(laddr), "r"(c));
    uint64_t u;
    asm volatile("ld.shared::cluster.b64 %0, [%1];" : "=l"(u) : "r"(raddr));
    float2 v;
    v.x = __uint_as_float((uint32_t)u);
    v.y = __uint_as_float((uint32_t)(u >> 32));
    return v;
}

__global__ void zero_kernel(float* __restrict__ out, int n) {
    int i = blockIdx.x * blockDim.x + threadIdx.x;
    if (i < n) out[i] = 0.0f;
}

__global__ void __launch_bounds__(THREADS, 2) __cluster_dims__(CLUSTER, 1, 1)
edge_cluster_kernel(const float* __restrict__ T, const float* __restrict__ cp,
                    const float* __restrict__ L, const float* __restrict__ C,
                    const float* __restrict__ A, const int* __restrict__ S,
                    const int* __restrict__ D, const float* __restrict__ ts,
                    float* __restrict__ out, int nq, int ne, int n) {
    extern __shared__ float2 tile[];   // NPC entries = 100,000 B
    uint32_t rank;
    asm("mov.u32 %0, %%cluster_ctarank;" : "=r"(rank));

    // Load my 12,500-node slice (coalesced; table is L2-resident after wave 1).
    int base = (int)(rank * NPC);
    for (int i = threadIdx.x; i < (int)NPC; i += THREADS) {
        int node = base + i;
        float tv = 0.0f, cv = 1.0f;
        if (node < n) { tv = T[node]; cv = cp[node]; }
        tile[i] = make_float2(tv, cv);
    }
    // All slices visible before any peer gathers.
    asm volatile("barrier.cluster.arrive.aligned;" ::: "memory");
    asm volatile("barrier.cluster.wait.aligned;"   ::: "memory");

    uint32_t sb = smem_u32(tile);
    float t = __ldg(ts);

    int  gtid   = blockIdx.x * THREADS + threadIdx.x;
    int  stride = gridDim.x * THREADS;
    for (int q = gtid; q < nq; q += stride) {
        int e0 = q * 4;
        if (e0 + 3 < ne) {
            int4   s = __ldg(reinterpret_cast<const int4*>(S) + q);
            int4   d = __ldg(reinterpret_cast<const int4*>(D) + q);
            float4 l = __ldg(reinterpret_cast<const float4*>(L) + q);
            float4 c = __ldg(reinterpret_cast<const float4*>(C) + q);
            float4 a = __ldg(reinterpret_cast<const float4*>(A) + q);

            float2 n0s = dsm_read(sb, (uint32_t)s.x), n0d = dsm_read(sb, (uint32_t)d.x);
            float2 n1s = dsm_read(sb, (uint32_t)s.y), n1d = dsm_read(sb, (uint32_t)d.y);
            float2 n2s = dsm_read(sb, (uint32_t)s.z), n2d = dsm_read(sb, (uint32_t)d.z);
            float2 n3s = dsm_read(sb, (uint32_t)s.w), n3d = dsm_read(sb, (uint32_t)d.w);

            edge_op(n0s.x, n0s.y, n0d.x, n0d.y, l.x, c.x, a.x, t, s.x, d.x, out);
            edge_op(n1s.x, n1s.y, n1d.x, n1d.y, l.y, c.y, a.y, t, s.y, d.y, out);
            edge_op(n2s.x, n2s.y, n2d.x, n2d.y, l.z, c.z, a.z, t, s.z, d.z, out);
            edge_op(n3s.x, n3s.y, n3d.x, n3d.y, l.w, c.w, a.w, t, s.w, d.w, out);
        } else {
            for (int e = e0; e < ne; ++e) {
                int si = S[e], di = D[e];
                float2 ns = dsm_read(sb, (uint32_t)si);
                float2 nd = dsm_read(sb, (uint32_t)di);
                edge_op(ns.x, ns.y, nd.x, nd.y, L[e], C[e], A[e], t, si, di, out);
            }
        }
    }

    // No CTA may exit while cluster peers might still read its SMEM slice.
    asm volatile("barrier.cluster.arrive.aligned;" ::: "memory");
    asm volatile("barrier.cluster.wait.aligned;"   ::: "memory");
}

// ---------------- fallback path (previous best design) ----------------
__global__ void prep_kernel(const float* __restrict__ T,
                            const float* __restrict__ cp,
                            float* __restrict__ out, int n) {
    int i = blockIdx.x * blockDim.x + threadIdx.x;
    if (i < n) {
        out[i] = 0.0f;
        g_tc[i] = make_float2(T[i], cp[i]);
    }
}

__global__ void __launch_bounds__(256)
edge_kernel(const float* __restrict__ L, const float* __restrict__ C,
            const float* __restrict__ A, const int* __restrict__ S,
            const int* __restrict__ D, const float* __restrict__ ts,
            float* __restrict__ out, int nq, int ne) {
    int q = blockIdx.x * blockDim.x + threadIdx.x;
    if (q >= nq) return;
    float t = __ldg(ts);
    int e0 = q * 4;
    if (e0 + 3 < ne) {
        int4   s = __ldg(reinterpret_cast<const int4*>(S) + q);
        int4   d = __ldg(reinterpret_cast<const int4*>(D) + q);
        float4 l = __ldg(reinterpret_cast<const float4*>(L) + q);
        float4 c = __ldg(reinterpret_cast<const float4*>(C) + q);
        float4 a = __ldg(reinterpret_cast<const float4*>(A) + q);
        float2 n0s = g_tc[s.x], n0d = g_tc[d.x];
        float2 n1s = g_tc[s.y], n1d = g_tc[d.y];
        float2 n2s = g_tc[s.z], n2d = g_tc[d.z];
        float2 n3s = g_tc[s.w], n3d = g_tc[d.w];
        edge_op(n0s.x, n0s.y, n0d.x, n0d.y, l.x, c.x, a.x, t, s.x, d.x, out);
        edge_op(n1s.x, n1s.y, n1d.x, n1d.y, l.y, c.y, a.y, t, s.y, d.y, out);
        edge_op(n2s.x, n2s.y, n2d.x, n2d.y, l.z, c.z, a.z, t, s.z, d.z, out);
        edge_op(n3s.x, n3s.y, n3d.x, n3d.y, l.w, c.w, a.w, t, s.w, d.w, out);
    } else {
        for (int e = e0; e < ne; ++e) {
            int si = S[e], di = D[e];
            float2 ns = g_tc[si], nd = g_tc[di];
            edge_op(ns.x, ns.y, nd.x, nd.y, L[e], C[e], A[e], t, si, di, out);
        }
    }
}

// ---------------- launch ----------------
extern "C" void kernel_launch(void* const* d_in, const int* in_sizes, int n_in,
                              void* d_out, int out_size) {
    const float* T    = (const float*)d_in[0];
    const float* cp   = (const float*)d_in[1];
    const float* L    = (const float*)d_in[2];
    const float* cond = (const float*)d_in[3];
    const float* A    = (const float*)d_in[4];
    const float* ts   = (const float*)d_in[5];
    const int*   src  = (const int*)d_in[6];
    const int*   dst  = (const int*)d_in[7];
    float*       out  = (float*)d_out;

    int n  = in_sizes[0];
    int ne = in_sizes[2];
    int nq = (ne + 3) / 4;

    if (n <= (int)(CLUSTER * NPC)) {
        // Cluster-DSMEM path (expected shape: n = 100,000).
        static bool attr_set = false;
        if (!attr_set) {
            cudaFuncSetAttribute(edge_cluster_kernel,
                                 cudaFuncAttributeMaxDynamicSharedMemorySize,
                                 (int)(NPC * sizeof(float2)));
            attr_set = true;
        }
        zero_kernel<<<(n + 255) / 256, 256>>>(out, n);
        edge_cluster_kernel<<<GRID_CTAS, THREADS, NPC * sizeof(float2)>>>(
            T, cp, L, cond, A, src, dst, ts, out, nq, ne, n);
    } else {
        // Fallback: global-gather path.
        prep_kernel<<<(n + 255) / 256, 256>>>(T, cp, out, n);
        edge_kernel<<<(nq + 255) / 256, 256>>>(L, cond, A, src, dst, ts, out, nq, ne);
    }
}

// round 11
// speedup vs baseline: 2.6405x; 2.6405x over previous
#include <cuda_runtime.h>

// Packed per-node {T, cp}: each endpoint gather is ONE 8-byte access
// (1 L1tex wavefront per lane) instead of two 4-byte accesses in two arrays.
// 131072 * 8 B = 1 MB static __device__ storage (no allocation).
#define MAX_NODES 131072
__device__ float2 g_tc[MAX_NODES];

// Kernel 1: zero the output accumulator and build the packed node array.
__global__ void prep_kernel(const float* __restrict__ T,
                            const float* __restrict__ cp,
                            float* __restrict__ out, int n) {
    int i = blockIdx.x * blockDim.x + threadIdx.x;
    if (i < n) {
        out[i] = 0.0f;
        g_tc[i] = make_float2(T[i], cp[i]);
    }
}

// Gather with L1 evict-last policy: node-table lines get L1 retention
// priority so the 128 MB of streaming edge traffic (default policy) cannot
// thrash the 800 KB table. Raises L1 hit rate on the 12.8M random gathers,
// cutting the ~300 MB of gather sector traffic hitting L2 (L2 was co-saturated
// at ~75% with L1 in R5-R7).
__device__ __forceinline__ float2 gather_node(const float2* __restrict__ p) {
    float2 v;
    asm volatile("ld.global.nc.L1::evict_last.v2.f32 {%0, %1}, [%2];"
                 : "=f"(v.x), "=f"(v.y) : "l"(p));
    return v;
}

__device__ __forceinline__ void edge_op(float Ts, float cps, float Td, float cpd,
                                        float L, float C, float A, float t,
                                        int si, int di, float* out) {
    float dT = Ts - Td;
    // relu: for ~50% of random edges dT <= 0 -> E == 0 exactly -> skip both
    // atomics (halves REDG lane count) and all the math.
    if (dT > 0.0f) {
        float x   = __fdividef(dT, L) * C;             // gradient * conductivity, > 0
        // cbrt(x) = 2^(log2(x)/3): 2 MUFU ops, rel err ~1e-6
        float hfd = exp2f(0.33333334f * __log2f(x));
        float Ec  = hfd * A * t;                        // conduction-limited energy
        float ccp = __fdividef(cpd * cps, cpd + cps);   // series thermal capacity
        float E   = fminf(Ec, dT * ccp);
        atomicAdd(out + di,  E);   // heat received (no return value -> REDG)
        atomicAdd(out + si, -E);   // heat sent
    }
}

// Kernel 2: 4 edges per thread (R5 champion structure).
// Edge-array reads: 128-bit coalesced vector loads, default cache policy.
// Node reads: 8 independent evict-last float2 gathers (MLP=8).
__global__ void __launch_bounds__(256)
edge_kernel(const float* __restrict__ L, const float* __restrict__ C,
            const float* __restrict__ A, const int* __restrict__ S,
            const int* __restrict__ D, const float* __restrict__ ts,
            float* __restrict__ out, int nq, int ne) {
    int q = blockIdx.x * blockDim.x + threadIdx.x;
    if (q >= nq) return;
    float t = __ldg(ts);
    int e0 = q * 4;
    if (e0 + 3 < ne) {
        int4   s = __ldg(reinterpret_cast<const int4*>(S) + q);
        int4   d = __ldg(reinterpret_cast<const int4*>(D) + q);
        float4 l = __ldg(reinterpret_cast<const float4*>(L) + q);
        float4 c = __ldg(reinterpret_cast<const float4*>(C) + q);
        float4 a = __ldg(reinterpret_cast<const float4*>(A) + q);

        // Issue all 8 gathers up front (independent -> overlapped in LSU).
        float2 n0s = gather_node(g_tc + s.x), n0d = gather_node(g_tc + d.x);
        float2 n1s = gather_node(g_tc + s.y), n1d = gather_node(g_tc + d.y);
        float2 n2s = gather_node(g_tc + s.z), n2d = gather_node(g_tc + d.z);
        float2 n3s = gather_node(g_tc + s.w), n3d = gather_node(g_tc + d.w);

        edge_op(n0s.x, n0s.y, n0d.x, n0d.y, l.x, c.x, a.x, t, s.x, d.x, out);
        edge_op(n1s.x, n1s.y, n1d.x, n1d.y, l.y, c.y, a.y, t, s.y, d.y, out);
        edge_op(n2s.x, n2s.y, n2d.x, n2d.y, l.z, c.z, a.z, t, s.z, d.z, out);
        edge_op(n3s.x, n3s.y, n3d.x, n3d.y, l.w, c.w, a.w, t, s.w, d.w, out);
    } else {
        // scalar tail (ne % 4 != 0); for this problem ne = 6,400,000 so unused
        for (int e = e0; e < ne; ++e) {
            int si = S[e], di = D[e];
            float2 ns = g_tc[si], nd = g_tc[di];
            edge_op(ns.x, ns.y, nd.x, nd.y, L[e], C[e], A[e], t, si, di, out);
        }
    }
}

extern "C" void kernel_launch(void* const* d_in, const int* in_sizes, int n_in,
                              void* d_out, int out_size) {
    const float* T    = (const float*)d_in[0];
    const float* cp   = (const float*)d_in[1];
    const float* L    = (const float*)d_in[2];
    const float* cond = (const float*)d_in[3];
    const float* A    = (const float*)d_in[4];
    const float* ts   = (const float*)d_in[5];
    const int*   src  = (const int*)d_in[6];
    const int*   dst  = (const int*)d_in[7];
    float*       out  = (float*)d_out;

    int n  = in_sizes[0];   // nodes (== out_size)
    int ne = in_sizes[2];   // edges

    prep_kernel<<<(n + 255) / 256, 256>>>(T, cp, out, n);

    int nq = (ne + 3) / 4;
    edge_kernel<<<(nq + 255) / 256, 256>>>(L, cond, A, src, dst, ts, out, nq, ne);
}

// round 12
// speedup vs baseline: 2.6416x; 1.0004x over previous
#include <cuda_runtime.h>

// Packed per-node {T, cp}: each endpoint gather is ONE 8-byte access
// (1 L1tex wavefront per lane). 1 MB static __device__ storage.
#define MAX_NODES 131072
__device__ float2 g_tc[MAX_NODES];

// Kernel 1: pack the node table (out is zeroed by a memset node).
__global__ void prep_kernel(const float* __restrict__ T,
                            const float* __restrict__ cp, int n) {
    int i = blockIdx.x * blockDim.x + threadIdx.x;
    if (i < n) g_tc[i] = make_float2(T[i], cp[i]);
}

// Gather with L1 evict-last: node-table lines keep L1 residency against the
// 128 MB of streaming edge traffic. ncu-verified: kernel 87.1 -> 78.3 us.
__device__ __forceinline__ float2 gather_node(const float2* __restrict__ p) {
    float2 v;
    asm volatile("ld.global.nc.L1::evict_last.v2.f32 {%0, %1}, [%2];"
                 : "=f"(v.x), "=f"(v.y) : "l"(p));
    return v;
}

__device__ __forceinline__ void edge_op(float Ts, float cps, float Td, float cpd,
                                        float L, float C, float A, float t,
                                        int si, int di, float* out) {
    float dT = Ts - Td;
    // relu: ~50% of random edges have dT <= 0 -> E == 0 exactly -> skip the
    // two REDG lanes and all math.
    if (dT > 0.0f) {
        float x   = __fdividef(dT, L) * C;
        float hfd = exp2f(0.33333334f * __log2f(x));   // cbrt via 2 MUFU
        float Ec  = hfd * A * t;
        float ccp = __fdividef(cpd * cps, cpd + cps);
        float E   = fminf(Ec, dT * ccp);
        atomicAdd(out + di,  E);
        atomicAdd(out + si, -E);
    }
}

// Kernel 2: EIGHT edges per thread (R11 change: double per-warp ILP).
// The binding pipe is LSU lane issue (L1=76% busy, 24% idle from dependency
// tails). 16 independent evict-last gathers + 10 coalesced 128-bit stream
// loads are front-batched per thread so the LSU stays fed through each
// edge_op math/RED tail. Occupancy drops (regs ~80) but R6 proved occupancy
// is not binding; in-flight lane count is.
__global__ void __launch_bounds__(256)
edge_kernel(const float* __restrict__ L, const float* __restrict__ C,
            const float* __restrict__ A, const int* __restrict__ S,
            const int* __restrict__ D, const float* __restrict__ ts,
            float* __restrict__ out, int nq, int ne) {
    int q = blockIdx.x * blockDim.x + threadIdx.x;   // one q = 8 edges
    if (q >= nq) return;
    float t = __ldg(ts);
    int e0 = q * 8;
    if (e0 + 7 < ne) {
        int4   s0 = __ldg(reinterpret_cast<const int4*>(S) + 2 * q);
        int4   s1 = __ldg(reinterpret_cast<const int4*>(S) + 2 * q + 1);
        int4   d0 = __ldg(reinterpret_cast<const int4*>(D) + 2 * q);
        int4   d1 = __ldg(reinterpret_cast<const int4*>(D) + 2 * q + 1);
        float4 l0 = __ldg(reinterpret_cast<const float4*>(L) + 2 * q);
        float4 l1 = __ldg(reinterpret_cast<const float4*>(L) + 2 * q + 1);
        float4 c0 = __ldg(reinterpret_cast<const float4*>(C) + 2 * q);
        float4 c1 = __ldg(reinterpret_cast<const float4*>(C) + 2 * q + 1);
        float4 a0 = __ldg(reinterpret_cast<const float4*>(A) + 2 * q);
        float4 a1 = __ldg(reinterpret_cast<const float4*>(A) + 2 * q + 1);

        // 16 independent gathers front-batched (MLP=16).
        float2 g0s = gather_node(g_tc + s0.x), g0d = gather_node(g_tc + d0.x);
        float2 g1s = gather_node(g_tc + s0.y), g1d = gather_node(g_tc + d0.y);
        float2 g2s = gather_node(g_tc + s0.z), g2d = gather_node(g_tc + d0.z);
        float2 g3s = gather_node(g_tc + s0.w), g3d = gather_node(g_tc + d0.w);
        float2 g4s = gather_node(g_tc + s1.x), g4d = gather_node(g_tc + d1.x);
        float2 g5s = gather_node(g_tc + s1.y), g5d = gather_node(g_tc + d1.y);
        float2 g6s = gather_node(g_tc + s1.z), g6d = gather_node(g_tc + d1.z);
        float2 g7s = gather_node(g_tc + s1.w), g7d = gather_node(g_tc + d1.w);

        edge_op(g0s.x, g0s.y, g0d.x, g0d.y, l0.x, c0.x, a0.x, t, s0.x, d0.x, out);
        edge_op(g1s.x, g1s.y, g1d.x, g1d.y, l0.y, c0.y, a0.y, t, s0.y, d0.y, out);
        edge_op(g2s.x, g2s.y, g2d.x, g2d.y, l0.z, c0.z, a0.z, t, s0.z, d0.z, out);
        edge_op(g3s.x, g3s.y, g3d.x, g3d.y, l0.w, c0.w, a0.w, t, s0.w, d0.w, out);
        edge_op(g4s.x, g4s.y, g4d.x, g4d.y, l1.x, c1.x, a1.x, t, s1.x, d1.x, out);
        edge_op(g5s.x, g5s.y, g5d.x, g5d.y, l1.y, c1.y, a1.y, t, s1.y, d1.y, out);
        edge_op(g6s.x, g6s.y, g6d.x, g6d.y, l1.z, c1.z, a1.z, t, s1.z, d1.z, out);
        edge_op(g7s.x, g7s.y, g7d.x, g7d.y, l1.w, c1.w, a1.w, t, s1.w, d1.w, out);
    } else {
        for (int e = e0; e < ne; ++e) {
            int si = S[e], di = D[e];
            float2 ns = g_tc[si], nd = g_tc[di];
            edge_op(ns.x, ns.y, nd.x, nd.y, L[e], C[e], A[e], t, si, di, out);
        }
    }
}

extern "C" void kernel_launch(void* const* d_in, const int* in_sizes, int n_in,
                              void* d_out, int out_size) {
    const float* T    = (const float*)d_in[0];
    const float* cp   = (const float*)d_in[1];
    const float* L    = (const float*)d_in[2];
    const float* cond = (const float*)d_in[3];
    const float* A    = (const float*)d_in[4];
    const float* ts   = (const float*)d_in[5];
    const int*   src  = (const int*)d_in[6];
    const int*   dst  = (const int*)d_in[7];
    float*       out  = (float*)d_out;

    int n  = in_sizes[0];   // nodes (== out_size)
    int ne = in_sizes[2];   // edges

    // Zero accumulator via a memset node; prep only packs the node table.
    cudaMemsetAsync(out, 0, (size_t)n * sizeof(float));
    prep_kernel<<<(n + 255) / 256, 256>>>(T, cp, n);

    int nq = (ne + 7) / 8;
    edge_kernel<<<(nq + 255) / 256, 256>>>(L, cond, A, src, dst, ts, out, nq, ne);
}